// round 6
// baseline (speedup 1.0000x reference)
#include <cuda_runtime.h>
#include <cuda_bf16.h>
#include <math.h>
#include <stdint.h>

// Problem constants
#define B_   2
#define T_   2048
#define H_   2048
#define NH_  16
#define HD_  128
#define FF_  8192
#define M_   (B_*T_)       // 4096
#define NBATCH (B_*NH_)    // 32
#define EPS_ 1e-5f

// ---------------- scratch (static device globals) ----------------
__device__ __align__(128) __nv_bfloat16 g_h_h [(size_t)M_*H_];
__device__ __align__(128) __nv_bfloat16 g_h_l [(size_t)M_*H_];
__device__ __align__(128) __nv_bfloat16 g_q_h [(size_t)M_*H_];
__device__ __align__(128) __nv_bfloat16 g_q_l [(size_t)M_*H_];
__device__ __align__(128) __nv_bfloat16 g_k_h [(size_t)M_*H_];
__device__ __align__(128) __nv_bfloat16 g_k_l [(size_t)M_*H_];
__device__ __align__(128) __nv_bfloat16 g_vt_h[(size_t)M_*H_];   // [B,NH,HD,T]
__device__ __align__(128) __nv_bfloat16 g_vt_l[(size_t)M_*H_];
__device__ __align__(128) __nv_bfloat16 g_at_h[(size_t)M_*H_];   // attn [B,T,H]
__device__ __align__(128) __nv_bfloat16 g_at_l[(size_t)M_*H_];
__device__ __align__(128) __nv_bfloat16 g_f_h [(size_t)M_*FF_];
__device__ __align__(128) __nv_bfloat16 g_f_l [(size_t)M_*FF_];
__device__ __align__(128) float g_x2[(size_t)M_*H_];
__device__ __align__(128) float g_sc[(size_t)NBATCH*T_*T_];
__device__ __align__(128) __nv_bfloat16 g_p_h[(size_t)NBATCH*T_*T_];
__device__ __align__(128) __nv_bfloat16 g_p_l[(size_t)NBATCH*T_*T_];
// transposed split weights [N,K]
__device__ __align__(128) __nv_bfloat16 g_wq_h[(size_t)H_*H_];
__device__ __align__(128) __nv_bfloat16 g_wq_l[(size_t)H_*H_];
__device__ __align__(128) __nv_bfloat16 g_wk_h[(size_t)H_*H_];
__device__ __align__(128) __nv_bfloat16 g_wk_l[(size_t)H_*H_];
__device__ __align__(128) __nv_bfloat16 g_wv_h[(size_t)H_*H_];
__device__ __align__(128) __nv_bfloat16 g_wv_l[(size_t)H_*H_];
__device__ __align__(128) __nv_bfloat16 g_wo_h[(size_t)H_*H_];
__device__ __align__(128) __nv_bfloat16 g_wo_l[(size_t)H_*H_];
__device__ __align__(128) __nv_bfloat16 g_w1_h[(size_t)FF_*H_];
__device__ __align__(128) __nv_bfloat16 g_w1_l[(size_t)FF_*H_];
__device__ __align__(128) __nv_bfloat16 g_w2_h[(size_t)H_*FF_];
__device__ __align__(128) __nv_bfloat16 g_w2_l[(size_t)H_*FF_];

// ---------------- PTX helpers (all arch-portable: sm_80+) ----------------
__device__ __forceinline__ uint32_t smem_u32(const void* p) {
    uint32_t a;
    asm("{ .reg .u64 t; cvta.to.shared.u64 t, %1; cvt.u32.u64 %0, t; }" : "=r"(a) : "l"(p));
    return a;
}
#define SW128(o) ((o) ^ (((o) >> 3) & 0x70))

__device__ __forceinline__ void cpa16(uint32_t s, const void* g) {
    asm volatile("cp.async.cg.shared.global [%0], [%1], 16;" :: "r"(s), "l"(g) : "memory");
}
__device__ __forceinline__ void cpa_commit() {
    asm volatile("cp.async.commit_group;" ::: "memory");
}
template<int N> __device__ __forceinline__ void cpa_wait() {
    asm volatile("cp.async.wait_group %0;" :: "n"(N) : "memory");
}

#define LDSM4(r, addr) \
    asm volatile("ldmatrix.sync.aligned.m8n8.x4.shared.b16 {%0,%1,%2,%3}, [%4];" \
        : "=r"((r)[0]), "=r"((r)[1]), "=r"((r)[2]), "=r"((r)[3]) : "r"(addr))

#define MMA_BF16(d, a, b) \
    asm volatile("mma.sync.aligned.m16n8k16.row.col.f32.bf16.bf16.f32 " \
        "{%0,%1,%2,%3},{%4,%5,%6,%7},{%8,%9},{%0,%1,%2,%3};" \
        : "+f"((d)[0]), "+f"((d)[1]), "+f"((d)[2]), "+f"((d)[3]) \
        : "r"((a)[0]), "r"((a)[1]), "r"((a)[2]), "r"((a)[3]), "r"((b)[0]), "r"((b)[1]))

// ---------------- misc helpers ----------------
__device__ __forceinline__ float gelu_tanh_f(float x) {
    float x3 = x * x * x;
    float t  = tanhf(0.7978845608028654f * (x + 0.044715f * x3));
    return 0.5f * x * (1.0f + t);
}
__device__ __forceinline__ void st_split2(__nv_bfloat16* ph, __nv_bfloat16* pl, float a, float b) {
    __nv_bfloat16 ha = __float2bfloat16(a), hb = __float2bfloat16(b);
    __nv_bfloat162 hp = __halves2bfloat162(ha, hb);
    __nv_bfloat162 lp = __halves2bfloat162(__float2bfloat16(a - __bfloat162float(ha)),
                                           __float2bfloat16(b - __bfloat162float(hb)));
    *(uint32_t*)ph = *(uint32_t*)&hp;
    *(uint32_t*)pl = *(uint32_t*)&lp;
}

// ---------------- weight transpose + split: W[K,N] f32 -> T[N,K] bf16 hi/lo ----------------
__global__ __launch_bounds__(256)
void wsplitT(const float* __restrict__ W, __nv_bfloat16* __restrict__ Th,
             __nv_bfloat16* __restrict__ Tl, int K, int N)
{
    __shared__ float t[32][33];
    int n0 = blockIdx.x * 32, k0 = blockIdx.y * 32;
    int tx = threadIdx.x, ty = threadIdx.y;   // (32,8)
#pragma unroll
    for (int r = ty; r < 32; r += 8)
        t[r][tx] = W[(size_t)(k0 + r) * N + n0 + tx];
    __syncthreads();
#pragma unroll
    for (int r = ty; r < 32; r += 8) {
        float v = t[tx][r];
        __nv_bfloat16 h = __float2bfloat16(v);
        size_t idx = (size_t)(n0 + r) * K + k0 + tx;
        Th[idx] = h;
        Tl[idx] = __float2bfloat16(v - __bfloat162float(h));
    }
}

// batched version for the four HxH weights (z = which weight)
__global__ __launch_bounds__(256)
void wsplitT4(const float* __restrict__ w0, const float* __restrict__ w1,
              const float* __restrict__ w2, const float* __restrict__ w3,
              __nv_bfloat16* __restrict__ t0h, __nv_bfloat16* __restrict__ t0l,
              __nv_bfloat16* __restrict__ t1h, __nv_bfloat16* __restrict__ t1l,
              __nv_bfloat16* __restrict__ t2h, __nv_bfloat16* __restrict__ t2l,
              __nv_bfloat16* __restrict__ t3h, __nv_bfloat16* __restrict__ t3l)
{
    __shared__ float t[32][33];
    int z = blockIdx.z;
    const float* W = (z == 0) ? w0 : (z == 1) ? w1 : (z == 2) ? w2 : w3;
    __nv_bfloat16* Th = (z == 0) ? t0h : (z == 1) ? t1h : (z == 2) ? t2h : t3h;
    __nv_bfloat16* Tl = (z == 0) ? t0l : (z == 1) ? t1l : (z == 2) ? t2l : t3l;
    int n0 = blockIdx.x * 32, k0 = blockIdx.y * 32;
    int tx = threadIdx.x, ty = threadIdx.y;
#pragma unroll
    for (int r = ty; r < 32; r += 8)
        t[r][tx] = W[(size_t)(k0 + r) * H_ + n0 + tx];
    __syncthreads();
#pragma unroll
    for (int r = ty; r < 32; r += 8) {
        float v = t[tx][r];
        __nv_bfloat16 h = __float2bfloat16(v);
        size_t idx = (size_t)(n0 + r) * H_ + k0 + tx;
        Th[idx] = h;
        Tl[idx] = __float2bfloat16(v - __bfloat162float(h));
    }
}

// ---------------- LayerNorm -> bf16 hi/lo ----------------
__global__ __launch_bounds__(256)
void ln_kernel(const float* __restrict__ x, const float* __restrict__ sc,
               const float* __restrict__ sh,
               __nv_bfloat16* __restrict__ oh, __nv_bfloat16* __restrict__ ol)
{
    __shared__ float red[8];
    int row = blockIdx.x;
    int tid = threadIdx.x;
    const float* xr = x + (size_t)row * H_;

    float v[8];
    float s = 0.f;
#pragma unroll
    for (int i = 0; i < 8; i++) { v[i] = xr[i * 256 + tid]; s += v[i]; }
#pragma unroll
    for (int o = 16; o > 0; o >>= 1) s += __shfl_xor_sync(0xffffffffu, s, o);
    if ((tid & 31) == 0) red[tid >> 5] = s;
    __syncthreads();
    float tot = 0.f;
#pragma unroll
    for (int i = 0; i < 8; i++) tot += red[i];
    __syncthreads();
    float mean = tot * (1.0f / H_);

    float s2 = 0.f;
#pragma unroll
    for (int i = 0; i < 8; i++) { float d = v[i] - mean; s2 += d * d; }
#pragma unroll
    for (int o = 16; o > 0; o >>= 1) s2 += __shfl_xor_sync(0xffffffffu, s2, o);
    if ((tid & 31) == 0) red[tid >> 5] = s2;
    __syncthreads();
    float tot2 = 0.f;
#pragma unroll
    for (int i = 0; i < 8; i++) tot2 += red[i];

    float inv = rsqrtf(tot2 * (1.0f / H_) + EPS_);
    size_t rb = (size_t)row * H_;
#pragma unroll
    for (int i = 0; i < 8; i++) {
        int col = i * 256 + tid;
        float val = sc[col] * ((v[i] - mean) * inv) + sh[col];
        __nv_bfloat16 h = __float2bfloat16(val);
        oh[rb + col] = h;
        ol[rb + col] = __float2bfloat16(val - __bfloat162float(h));
    }
}

// ---------------- causal softmax: f32 scores -> bf16 hi/lo probs ----------------
__global__ __launch_bounds__(256)
void softmax_kernel(const float* __restrict__ sc,
                    __nv_bfloat16* __restrict__ ph, __nv_bfloat16* __restrict__ pl)
{
    __shared__ float red[8];
    int gid = blockIdx.x;
    int i   = gid & (T_ - 1);
    int tid = threadIdx.x;
    const float* row = sc + (size_t)gid * T_;

    int n = i + 1;
    int kround = ((i >> 7) + 1) << 7;

    float v[8];
    float mx = -1e30f;
#pragma unroll
    for (int s = 0; s < 8; s++) {
        int j = s * 256 + tid;
        v[s] = (j < n) ? row[j] : -1e30f;
        mx = fmaxf(mx, v[s]);
    }
#pragma unroll
    for (int o = 16; o > 0; o >>= 1) mx = fmaxf(mx, __shfl_xor_sync(0xffffffffu, mx, o));
    if ((tid & 31) == 0) red[tid >> 5] = mx;
    __syncthreads();
    float m2 = -1e30f;
#pragma unroll
    for (int w = 0; w < 8; w++) m2 = fmaxf(m2, red[w]);
    __syncthreads();

    float sum = 0.f;
#pragma unroll
    for (int s = 0; s < 8; s++) {
        int j = s * 256 + tid;
        if (j < n) { v[s] = __expf(v[s] - m2); sum += v[s]; }
        else       { v[s] = 0.f; }
    }
#pragma unroll
    for (int o = 16; o > 0; o >>= 1) sum += __shfl_xor_sync(0xffffffffu, sum, o);
    if ((tid & 31) == 0) red[tid >> 5] = sum;
    __syncthreads();
    float tot = 0.f;
#pragma unroll
    for (int w = 0; w < 8; w++) tot += red[w];

    float inv = 1.0f / tot;
    size_t rb = (size_t)gid * T_;
#pragma unroll
    for (int s = 0; s < 8; s++) {
        int j = s * 256 + tid;
        if (j < kround) {
            float p = v[s] * inv;
            __nv_bfloat16 hb = __float2bfloat16(p);
            ph[rb + j] = hb;
            pl[rb + j] = __float2bfloat16(p - __bfloat162float(hb));
        }
    }
}

// ---------------- mma.sync split-bf16 GEMM, 3-stage pipeline ----------------
// C[M,N] = (Ah+Al)[M,K] @ (Bh+Bl)[N,K]^T   (fp32 accum)
// CTA tile 128x128xBK64; 8 warps, warp tile 32x64 (grid 4m x 2n).
// EPI: 0 scores f32 batched (causal skip); 1 q/k permuted hi/lo (*alpha);
//      3 v transposed hi/lo; 4 AV -> attn hi/lo (K-limited); 5 Wo+res -> f32;
//      6 bias+gelu -> hi/lo; 7 bias+res -> f32 out
template<int EPI>
__global__ __launch_bounds__(256)
void mgemm(const __nv_bfloat16* __restrict__ Ah, const __nv_bfloat16* __restrict__ Al,
           const __nv_bfloat16* __restrict__ Bh, const __nv_bfloat16* __restrict__ Bl,
           float* __restrict__ Cf, __nv_bfloat16* __restrict__ Ch, __nv_bfloat16* __restrict__ Cl,
           const float* __restrict__ bias, const float* __restrict__ res,
           int K, int lda, int ldb, float alpha, size_t sA, size_t sB)
{
    int bn = blockIdx.x, bm = blockIdx.y, z = blockIdx.z;
    if (EPI == 0 && bn > bm) return;            // causal block skip
    int Keff = K;
    if (EPI == 4) { int kl = (bm + 1) * 128; if (kl < Keff) Keff = kl; }
    const int NCH = Keff >> 6;

    extern __shared__ char smem[];
    uint32_t sb = smem_u32(smem);
    // per stage: Ah @0, Al @16K, Bh @32K, Bl @48K; stage stride 64K; 3 stages
    const uint32_t STG = 65536;

    int tid = threadIdx.x, wid = tid >> 5, lane = tid & 31;
    int wm = wid >> 1, wn = wid & 1;            // warp tile: rows wm*32, cols wn*64

    const __nv_bfloat16* Agh = Ah + (size_t)z * sA + (size_t)(bm * 128) * lda;
    const __nv_bfloat16* Agl = Al + (size_t)z * sA + (size_t)(bm * 128) * lda;
    const __nv_bfloat16* Bgh = Bh + (size_t)z * sB + (size_t)(bn * 128) * ldb;
    const __nv_bfloat16* Bgl = Bl + (size_t)z * sB + (size_t)(bn * 128) * ldb;

    auto ldst = [&](int i, int st) {
        uint32_t base = sb + st * STG;
        int k0 = i << 6;
#pragma unroll
        for (int p = tid; p < 1024; p += 256) {
            int r = p >> 3, c = p & 7;
            uint32_t so = SW128(r * 128 + c * 16);
            size_t go = (size_t)r * lda + k0 + c * 8;
            cpa16(base + so,         Agh + go);
            cpa16(base + 16384 + so, Agl + go);
        }
#pragma unroll
        for (int p = tid; p < 1024; p += 256) {
            int r = p >> 3, c = p & 7;
            uint32_t so = SW128(r * 128 + c * 16);
            size_t go = (size_t)r * ldb + k0 + c * 8;
            cpa16(base + 32768 + so, Bgh + go);
            cpa16(base + 49152 + so, Bgl + go);
        }
        cpa_commit();
    };

    float acc[2][8][4];
#pragma unroll
    for (int mi = 0; mi < 2; mi++)
#pragma unroll
        for (int ni = 0; ni < 8; ni++)
#pragma unroll
            for (int r = 0; r < 4; r++) acc[mi][ni][r] = 0.f;

    // prologue: fill up to 2 stages
    ldst(0, 0);
    if (NCH > 1) ldst(1, 1);

    for (int i = 0; i < NCH; i++) {
        int st = i % 3;
        // stage i is complete when pending groups <= issued-(i+1); issued=min(NCH,i+2)
        if (i + 2 <= NCH) cpa_wait<1>();
        else              cpa_wait<0>();
        __syncthreads();          // data visible + all warps done with stage (i-1)%3... (i+2)%3 free
        if (i + 2 < NCH) ldst(i + 2, (i + 2) % 3);

        uint32_t base = sb + st * STG;
#pragma unroll
        for (int ks = 0; ks < 4; ks++) {
            uint32_t ah[2][4], al[2][4];
#pragma unroll
            for (int mi = 0; mi < 2; mi++) {
                int row = wm * 32 + mi * 16 + (lane & 15);
                uint32_t kb = ks * 32 + ((lane >> 4) << 4);
                uint32_t ad = base + SW128((uint32_t)(row * 128) + kb);
                LDSM4(ah[mi], ad);
                LDSM4(al[mi], ad + 16384);
            }
            uint32_t bh[4][4], bl[4][4];
#pragma unroll
            for (int g = 0; g < 4; g++) {
                int nrow = wn * 64 + g * 16 + (lane & 7) + ((lane >> 4) << 3);
                uint32_t kb = ks * 32 + (((lane >> 3) & 1) << 4);
                uint32_t ad = base + 32768 + SW128((uint32_t)(nrow * 128) + kb);
                LDSM4(bh[g], ad);
                LDSM4(bl[g], ad + 16384);
            }
#pragma unroll
            for (int mi = 0; mi < 2; mi++)
#pragma unroll
                for (int ni = 0; ni < 8; ni++) {
                    uint32_t* pbh = &bh[ni >> 1][(ni & 1) * 2];
                    uint32_t* pbl = &bl[ni >> 1][(ni & 1) * 2];
                    MMA_BF16(acc[mi][ni], ah[mi], pbh);
                    MMA_BF16(acc[mi][ni], ah[mi], pbl);
                    MMA_BF16(acc[mi][ni], al[mi], pbh);
                }
        }
        // NOTE: no trailing sync — next iteration's barrier protects buffer reuse
    }

    // ---------------- epilogue (fragment layout) ----------------
#pragma unroll
    for (int mi = 0; mi < 2; mi++) {
#pragma unroll
        for (int ni = 0; ni < 8; ni++) {
            int row0 = bm * 128 + wm * 32 + mi * 16 + (lane >> 2);
            int col  = bn * 128 + wn * 64 + ni * 8 + (lane & 3) * 2;
#pragma unroll
            for (int half = 0; half < 2; half++) {
                int gm = row0 + half * 8;
                float v0 = acc[mi][ni][half * 2 + 0];
                float v1 = acc[mi][ni][half * 2 + 1];

                if (EPI == 0) {
                    float2* p = (float2*)(Cf + (size_t)z * T_ * T_ + (size_t)gm * T_ + col);
                    *p = make_float2(v0, v1);
                } else if (EPI == 1) {
                    v0 *= alpha; v1 *= alpha;
                    int b = gm >> 11, t = gm & (T_ - 1);
                    int hh = col >> 7, d = col & 127;
                    size_t idx = (((size_t)(b * NH_ + hh) * T_ + t) << 7) + d;
                    st_split2(Ch + idx, Cl + idx, v0, v1);
                } else if (EPI == 3) {
                    int b = gm >> 11, t = gm & (T_ - 1);
                    int hh = col >> 7, d = col & 127;
                    size_t i0 = ((((size_t)(b * NH_ + hh)) << 7) + d) * T_ + t;
                    __nv_bfloat16 h0 = __float2bfloat16(v0);
                    __nv_bfloat16 h1 = __float2bfloat16(v1);
                    Ch[i0] = h0;        Cl[i0] = __float2bfloat16(v0 - __bfloat162float(h0));
                    Ch[i0 + T_] = h1;   Cl[i0 + T_] = __float2bfloat16(v1 - __bfloat162float(h1));
                } else if (EPI == 4) {
                    int b = z >> 4, hh = z & 15;
                    size_t idx = ((size_t)(b * T_ + gm)) * H_ + hh * HD_ + col;
                    st_split2(Ch + idx, Cl + idx, v0, v1);
                } else if (EPI == 5) {
                    size_t idx = (size_t)gm * H_ + col;
                    float2 rv = *(const float2*)(res + idx);
                    *(float2*)(Cf + idx) = make_float2(v0 + rv.x, v1 + rv.y);
                } else if (EPI == 6) {
                    v0 = gelu_tanh_f(v0 + bias[col]);
                    v1 = gelu_tanh_f(v1 + bias[col + 1]);
                    size_t idx = (size_t)gm * FF_ + col;
                    st_split2(Ch + idx, Cl + idx, v0, v1);
                } else if (EPI == 7) {
                    size_t idx = (size_t)gm * H_ + col;
                    float2 rv = *(const float2*)(res + idx);
                    *(float2*)(Cf + idx) =
                        make_float2(v0 + rv.x + bias[col], v1 + rv.y + bias[col + 1]);
                }
            }
        }
    }
}

// ---------------- launch ----------------
extern "C" void kernel_launch(void* const* d_in, const int* in_sizes, int n_in,
                              void* d_out, int out_size)
{
    (void)in_sizes; (void)n_in; (void)out_size;
    const float* x    = (const float*)d_in[0];
    const float* wq   = (const float*)d_in[1];
    const float* wk   = (const float*)d_in[2];
    const float* wv   = (const float*)d_in[3];
    const float* wo   = (const float*)d_in[4];
    const float* ln1s = (const float*)d_in[5];
    const float* ln1b = (const float*)d_in[6];
    const float* ln2s = (const float*)d_in[7];
    const float* ln2b = (const float*)d_in[8];
    const float* w1   = (const float*)d_in[9];
    const float* b1   = (const float*)d_in[10];
    const float* w2   = (const float*)d_in[11];
    const float* b2   = (const float*)d_in[12];
    float* out = (float*)d_out;

    __nv_bfloat16 *h_h,*h_l,*q_h,*q_l,*k_h,*k_l,*vt_h,*vt_l,*at_h,*at_l,*f_h,*f_l,*p_h,*p_l;
    __nv_bfloat16 *wqt_h,*wqt_l,*wkt_h,*wkt_l,*wvt_h,*wvt_l,*wot_h,*wot_l,*w1t_h,*w1t_l,*w2t_h,*w2t_l;
    float *x2, *sc;
    cudaGetSymbolAddress((void**)&h_h, g_h_h);   cudaGetSymbolAddress((void**)&h_l, g_h_l);
    cudaGetSymbolAddress((void**)&q_h, g_q_h);   cudaGetSymbolAddress((void**)&q_l, g_q_l);
    cudaGetSymbolAddress((void**)&k_h, g_k_h);   cudaGetSymbolAddress((void**)&k_l, g_k_l);
    cudaGetSymbolAddress((void**)&vt_h, g_vt_h); cudaGetSymbolAddress((void**)&vt_l, g_vt_l);
    cudaGetSymbolAddress((void**)&at_h, g_at_h); cudaGetSymbolAddress((void**)&at_l, g_at_l);
    cudaGetSymbolAddress((void**)&f_h, g_f_h);   cudaGetSymbolAddress((void**)&f_l, g_f_l);
    cudaGetSymbolAddress((void**)&p_h, g_p_h);   cudaGetSymbolAddress((void**)&p_l, g_p_l);
    cudaGetSymbolAddress((void**)&wqt_h, g_wq_h); cudaGetSymbolAddress((void**)&wqt_l, g_wq_l);
    cudaGetSymbolAddress((void**)&wkt_h, g_wk_h); cudaGetSymbolAddress((void**)&wkt_l, g_wk_l);
    cudaGetSymbolAddress((void**)&wvt_h, g_wv_h); cudaGetSymbolAddress((void**)&wvt_l, g_wv_l);
    cudaGetSymbolAddress((void**)&wot_h, g_wo_h); cudaGetSymbolAddress((void**)&wot_l, g_wo_l);
    cudaGetSymbolAddress((void**)&w1t_h, g_w1_h); cudaGetSymbolAddress((void**)&w1t_l, g_w1_l);
    cudaGetSymbolAddress((void**)&w2t_h, g_w2_h); cudaGetSymbolAddress((void**)&w2t_l, g_w2_l);
    cudaGetSymbolAddress((void**)&x2, g_x2);
    cudaGetSymbolAddress((void**)&sc, g_sc);

    const int SMEM = 196608;   // 3 stages x 64KB
    cudaFuncSetAttribute(mgemm<0>, cudaFuncAttributeMaxDynamicSharedMemorySize, SMEM);
    cudaFuncSetAttribute(mgemm<1>, cudaFuncAttributeMaxDynamicSharedMemorySize, SMEM);
    cudaFuncSetAttribute(mgemm<3>, cudaFuncAttributeMaxDynamicSharedMemorySize, SMEM);
    cudaFuncSetAttribute(mgemm<4>, cudaFuncAttributeMaxDynamicSharedMemorySize, SMEM);
    cudaFuncSetAttribute(mgemm<5>, cudaFuncAttributeMaxDynamicSharedMemorySize, SMEM);
    cudaFuncSetAttribute(mgemm<6>, cudaFuncAttributeMaxDynamicSharedMemorySize, SMEM);
    cudaFuncSetAttribute(mgemm<7>, cudaFuncAttributeMaxDynamicSharedMemorySize, SMEM);

    const float qscale = 0.08838834764831843f;  // 1/sqrt(128)
    dim3 tt(32, 8);

    // weight transpose+split (4 square weights batched + the two FFN weights)
    wsplitT4<<<dim3(H_/32, H_/32, 4), tt>>>(wq, wk, wv, wo,
        wqt_h, wqt_l, wkt_h, wkt_l, wvt_h, wvt_l, wot_h, wot_l);
    wsplitT<<<dim3(FF_/32, H_/32),  tt>>>(w1, w1t_h, w1t_l, H_,  FF_);
    wsplitT<<<dim3(H_/32,  FF_/32), tt>>>(w2, w2t_h, w2t_l, FF_, H_);

    // LN1
    ln_kernel<<<M_, 256>>>(x, ln1s, ln1b, h_h, h_l);

    // QKV (q,k: EPI1 permuted; v: EPI3 transposed)
    dim3 gqkv(H_/128, M_/128);
    mgemm<1><<<gqkv, 256, SMEM>>>(h_h, h_l, wqt_h, wqt_l, nullptr, q_h, q_l,
                                  nullptr, nullptr, H_, H_, H_, qscale, 0, 0);
    mgemm<1><<<gqkv, 256, SMEM>>>(h_h, h_l, wkt_h, wkt_l, nullptr, k_h, k_l,
                                  nullptr, nullptr, H_, H_, H_, 1.0f, 0, 0);
    mgemm<3><<<gqkv, 256, SMEM>>>(h_h, h_l, wvt_h, wvt_l, nullptr, vt_h, vt_l,
                                  nullptr, nullptr, H_, H_, H_, 1.0f, 0, 0);

    // scores = q @ k^T (batched, causal block skip)
    dim3 gsc(T_/128, T_/128, NBATCH);
    mgemm<0><<<gsc, 256, SMEM>>>(q_h, q_l, k_h, k_l, sc, nullptr, nullptr,
                                 nullptr, nullptr, HD_, HD_, HD_, 1.0f,
                                 (size_t)T_*HD_, (size_t)T_*HD_);

    // softmax -> probs hi/lo
    softmax_kernel<<<NBATCH * T_, 256>>>(sc, p_h, p_l);

    // attn = P @ V (K-limited)
    dim3 gav(1, T_/128, NBATCH);
    mgemm<4><<<gav, 256, SMEM>>>(p_h, p_l, vt_h, vt_l, nullptr, at_h, at_l,
                                 nullptr, nullptr, T_, T_, T_, 1.0f,
                                 (size_t)T_*T_, (size_t)HD_*T_);

    // x2 = x + attn @ wo
    mgemm<5><<<gqkv, 256, SMEM>>>(at_h, at_l, wot_h, wot_l, x2, nullptr, nullptr,
                                  nullptr, x, H_, H_, H_, 1.0f, 0, 0);

    // LN2
    ln_kernel<<<M_, 256>>>(x2, ln2s, ln2b, h_h, h_l);

    // ffn = gelu(h @ w1 + b1)
    dim3 gf1(FF_/128, M_/128);
    mgemm<6><<<gf1, 256, SMEM>>>(h_h, h_l, w1t_h, w1t_l, nullptr, f_h, f_l,
                                 b1, nullptr, H_, H_, H_, 1.0f, 0, 0);

    // out = x2 + ffn @ w2 + b2
    dim3 gf2(H_/128, M_/128);
    mgemm<7><<<gf2, 256, SMEM>>>(f_h, f_l, w2t_h, w2t_l, out, nullptr, nullptr,
                                 b2, x2, FF_, FF_, FF_, 1.0f, 0, 0);
}

// round 8
// speedup vs baseline: 1.0441x; 1.0441x over previous
#include <cuda_runtime.h>
#include <cuda_bf16.h>
#include <math.h>
#include <stdint.h>

// Problem constants
#define B_   2
#define T_   2048
#define H_   2048
#define NH_  16
#define HD_  128
#define FF_  8192
#define M_   (B_*T_)       // 4096
#define NBATCH (B_*NH_)    // 32
#define EPS_ 1e-5f

// ---------------- scratch (static device globals) ----------------
__device__ __align__(128) __nv_bfloat16 g_h_h [(size_t)M_*H_];
__device__ __align__(128) __nv_bfloat16 g_h_l [(size_t)M_*H_];
__device__ __align__(128) __nv_bfloat16 g_q_h [(size_t)M_*H_];
__device__ __align__(128) __nv_bfloat16 g_q_l [(size_t)M_*H_];
__device__ __align__(128) __nv_bfloat16 g_k_h [(size_t)M_*H_];
__device__ __align__(128) __nv_bfloat16 g_k_l [(size_t)M_*H_];
__device__ __align__(128) __nv_bfloat16 g_vt_h[(size_t)M_*H_];   // [B,NH,HD,T]
__device__ __align__(128) __nv_bfloat16 g_vt_l[(size_t)M_*H_];
__device__ __align__(128) __nv_bfloat16 g_at_h[(size_t)M_*H_];   // attn [B,T,H]
__device__ __align__(128) __nv_bfloat16 g_at_l[(size_t)M_*H_];
__device__ __align__(128) __nv_bfloat16 g_f_h [(size_t)M_*FF_];
__device__ __align__(128) __nv_bfloat16 g_f_l [(size_t)M_*FF_];
__device__ __align__(128) float g_x2[(size_t)M_*H_];
__device__ __align__(128) float g_sc[(size_t)NBATCH*T_*T_];
__device__ __align__(128) __nv_bfloat16 g_p_h[(size_t)NBATCH*T_*T_];
__device__ __align__(128) __nv_bfloat16 g_p_l[(size_t)NBATCH*T_*T_];
// transposed split weights [N,K]
__device__ __align__(128) __nv_bfloat16 g_wq_h[(size_t)H_*H_];
__device__ __align__(128) __nv_bfloat16 g_wq_l[(size_t)H_*H_];
__device__ __align__(128) __nv_bfloat16 g_wk_h[(size_t)H_*H_];
__device__ __align__(128) __nv_bfloat16 g_wk_l[(size_t)H_*H_];
__device__ __align__(128) __nv_bfloat16 g_wv_h[(size_t)H_*H_];
__device__ __align__(128) __nv_bfloat16 g_wv_l[(size_t)H_*H_];
__device__ __align__(128) __nv_bfloat16 g_wo_h[(size_t)H_*H_];
__device__ __align__(128) __nv_bfloat16 g_wo_l[(size_t)H_*H_];
__device__ __align__(128) __nv_bfloat16 g_w1_h[(size_t)FF_*H_];
__device__ __align__(128) __nv_bfloat16 g_w1_l[(size_t)FF_*H_];
__device__ __align__(128) __nv_bfloat16 g_w2_h[(size_t)H_*FF_];
__device__ __align__(128) __nv_bfloat16 g_w2_l[(size_t)H_*FF_];

// ---------------- PTX helpers (all arch-portable: sm_80+) ----------------
__device__ __forceinline__ uint32_t smem_u32(const void* p) {
    uint32_t a;
    asm("{ .reg .u64 t; cvta.to.shared.u64 t, %1; cvt.u32.u64 %0, t; }" : "=r"(a) : "l"(p));
    return a;
}
#define SW128(o) ((o) ^ (((o) >> 3) & 0x70))

__device__ __forceinline__ void cpa16(uint32_t s, const void* g) {
    asm volatile("cp.async.cg.shared.global [%0], [%1], 16;" :: "r"(s), "l"(g) : "memory");
}
__device__ __forceinline__ void cpa_commit() {
    asm volatile("cp.async.commit_group;" ::: "memory");
}
template<int N> __device__ __forceinline__ void cpa_wait() {
    asm volatile("cp.async.wait_group %0;" :: "n"(N) : "memory");
}

#define LDSM4(r, addr) \
    asm volatile("ldmatrix.sync.aligned.m8n8.x4.shared.b16 {%0,%1,%2,%3}, [%4];" \
        : "=r"((r)[0]), "=r"((r)[1]), "=r"((r)[2]), "=r"((r)[3]) : "r"(addr))

#define MMA_BF16(d, a, b) \
    asm volatile("mma.sync.aligned.m16n8k16.row.col.f32.bf16.bf16.f32 " \
        "{%0,%1,%2,%3},{%4,%5,%6,%7},{%8,%9},{%0,%1,%2,%3};" \
        : "+f"((d)[0]), "+f"((d)[1]), "+f"((d)[2]), "+f"((d)[3]) \
        : "r"((a)[0]), "r"((a)[1]), "r"((a)[2]), "r"((a)[3]), "r"((b)[0]), "r"((b)[1]))

// ---------------- misc helpers ----------------
__device__ __forceinline__ float gelu_tanh_f(float x) {
    float x3 = x * x * x;
    float t  = tanhf(0.7978845608028654f * (x + 0.044715f * x3));
    return 0.5f * x * (1.0f + t);
}
__device__ __forceinline__ void st_split2(__nv_bfloat16* ph, __nv_bfloat16* pl, float a, float b) {
    __nv_bfloat16 ha = __float2bfloat16(a), hb = __float2bfloat16(b);
    __nv_bfloat162 hp = __halves2bfloat162(ha, hb);
    __nv_bfloat162 lp = __halves2bfloat162(__float2bfloat16(a - __bfloat162float(ha)),
                                           __float2bfloat16(b - __bfloat162float(hb)));
    *(uint32_t*)ph = *(uint32_t*)&hp;
    *(uint32_t*)pl = *(uint32_t*)&lp;
}
__device__ __forceinline__ uint32_t pack_split_hi(float a, float b, uint32_t* lo) {
    __nv_bfloat16 ha = __float2bfloat16(a), hb = __float2bfloat16(b);
    __nv_bfloat162 hp = __halves2bfloat162(ha, hb);
    __nv_bfloat162 lp = __halves2bfloat162(__float2bfloat16(a - __bfloat162float(ha)),
                                           __float2bfloat16(b - __bfloat162float(hb)));
    *lo = *(uint32_t*)&lp;
    return *(uint32_t*)&hp;
}

// ---------------- weight transpose + split: W[K,N] f32 -> T[N,K] bf16 hi/lo ----------------
__global__ __launch_bounds__(256)
void wsplitT(const float* __restrict__ W, __nv_bfloat16* __restrict__ Th,
             __nv_bfloat16* __restrict__ Tl, int K, int N)
{
    __shared__ float t[32][33];
    int n0 = blockIdx.x * 32, k0 = blockIdx.y * 32;
    int tx = threadIdx.x, ty = threadIdx.y;   // (32,8)
#pragma unroll
    for (int r = ty; r < 32; r += 8)
        t[r][tx] = W[(size_t)(k0 + r) * N + n0 + tx];
    __syncthreads();
#pragma unroll
    for (int r = ty; r < 32; r += 8) {
        float v = t[tx][r];
        __nv_bfloat16 h = __float2bfloat16(v);
        size_t idx = (size_t)(n0 + r) * K + k0 + tx;
        Th[idx] = h;
        Tl[idx] = __float2bfloat16(v - __bfloat162float(h));
    }
}

// batched version for the four HxH weights (z = which weight)
__global__ __launch_bounds__(256)
void wsplitT4(const float* __restrict__ w0, const float* __restrict__ w1,
              const float* __restrict__ w2, const float* __restrict__ w3,
              __nv_bfloat16* __restrict__ t0h, __nv_bfloat16* __restrict__ t0l,
              __nv_bfloat16* __restrict__ t1h, __nv_bfloat16* __restrict__ t1l,
              __nv_bfloat16* __restrict__ t2h, __nv_bfloat16* __restrict__ t2l,
              __nv_bfloat16* __restrict__ t3h, __nv_bfloat16* __restrict__ t3l)
{
    __shared__ float t[32][33];
    int z = blockIdx.z;
    const float* W = (z == 0) ? w0 : (z == 1) ? w1 : (z == 2) ? w2 : w3;
    __nv_bfloat16* Th = (z == 0) ? t0h : (z == 1) ? t1h : (z == 2) ? t2h : t3h;
    __nv_bfloat16* Tl = (z == 0) ? t0l : (z == 1) ? t1l : (z == 2) ? t2l : t3l;
    int n0 = blockIdx.x * 32, k0 = blockIdx.y * 32;
    int tx = threadIdx.x, ty = threadIdx.y;
#pragma unroll
    for (int r = ty; r < 32; r += 8)
        t[r][tx] = W[(size_t)(k0 + r) * H_ + n0 + tx];
    __syncthreads();
#pragma unroll
    for (int r = ty; r < 32; r += 8) {
        float v = t[tx][r];
        __nv_bfloat16 h = __float2bfloat16(v);
        size_t idx = (size_t)(n0 + r) * H_ + k0 + tx;
        Th[idx] = h;
        Tl[idx] = __float2bfloat16(v - __bfloat162float(h));
    }
}

// ---------------- LayerNorm -> bf16 hi/lo ----------------
__global__ __launch_bounds__(256)
void ln_kernel(const float* __restrict__ x, const float* __restrict__ sc,
               const float* __restrict__ sh,
               __nv_bfloat16* __restrict__ oh, __nv_bfloat16* __restrict__ ol)
{
    __shared__ float red[8];
    int row = blockIdx.x;
    int tid = threadIdx.x;
    const float* xr = x + (size_t)row * H_;

    float v[8];
    float s = 0.f;
#pragma unroll
    for (int i = 0; i < 8; i++) { v[i] = xr[i * 256 + tid]; s += v[i]; }
#pragma unroll
    for (int o = 16; o > 0; o >>= 1) s += __shfl_xor_sync(0xffffffffu, s, o);
    if ((tid & 31) == 0) red[tid >> 5] = s;
    __syncthreads();
    float tot = 0.f;
#pragma unroll
    for (int i = 0; i < 8; i++) tot += red[i];
    __syncthreads();
    float mean = tot * (1.0f / H_);

    float s2 = 0.f;
#pragma unroll
    for (int i = 0; i < 8; i++) { float d = v[i] - mean; s2 += d * d; }
#pragma unroll
    for (int o = 16; o > 0; o >>= 1) s2 += __shfl_xor_sync(0xffffffffu, s2, o);
    if ((tid & 31) == 0) red[tid >> 5] = s2;
    __syncthreads();
    float tot2 = 0.f;
#pragma unroll
    for (int i = 0; i < 8; i++) tot2 += red[i];

    float inv = rsqrtf(tot2 * (1.0f / H_) + EPS_);
    size_t rb = (size_t)row * H_;
#pragma unroll
    for (int i = 0; i < 8; i++) {
        int col = i * 256 + tid;
        float val = sc[col] * ((v[i] - mean) * inv) + sh[col];
        __nv_bfloat16 h = __float2bfloat16(val);
        oh[rb + col] = h;
        ol[rb + col] = __float2bfloat16(val - __bfloat162float(h));
    }
}

// ---------------- causal softmax: f32 scores -> bf16 hi/lo probs ----------------
__global__ __launch_bounds__(256)
void softmax_kernel(const float* __restrict__ sc,
                    __nv_bfloat16* __restrict__ ph, __nv_bfloat16* __restrict__ pl)
{
    __shared__ float red[8];
    int gid = blockIdx.x;
    int i   = gid & (T_ - 1);
    int tid = threadIdx.x;
    const float* row = sc + (size_t)gid * T_;

    int n = i + 1;
    int kround = ((i >> 7) + 1) << 7;

    float v[8];
    float mx = -1e30f;
#pragma unroll
    for (int s = 0; s < 8; s++) {
        int j = s * 256 + tid;
        v[s] = (j < n) ? row[j] : -1e30f;
        mx = fmaxf(mx, v[s]);
    }
#pragma unroll
    for (int o = 16; o > 0; o >>= 1) mx = fmaxf(mx, __shfl_xor_sync(0xffffffffu, mx, o));
    if ((tid & 31) == 0) red[tid >> 5] = mx;
    __syncthreads();
    float m2 = -1e30f;
#pragma unroll
    for (int w = 0; w < 8; w++) m2 = fmaxf(m2, red[w]);
    __syncthreads();

    float sum = 0.f;
#pragma unroll
    for (int s = 0; s < 8; s++) {
        int j = s * 256 + tid;
        if (j < n) { v[s] = __expf(v[s] - m2); sum += v[s]; }
        else       { v[s] = 0.f; }
    }
#pragma unroll
    for (int o = 16; o > 0; o >>= 1) sum += __shfl_xor_sync(0xffffffffu, sum, o);
    if ((tid & 31) == 0) red[tid >> 5] = sum;
    __syncthreads();
    float tot = 0.f;
#pragma unroll
    for (int w = 0; w < 8; w++) tot += red[w];

    float inv = 1.0f / tot;
    size_t rb = (size_t)gid * T_;
#pragma unroll
    for (int s = 0; s < 8; s++) {
        int j = s * 256 + tid;
        if (j < kround) {
            float p = v[s] * inv;
            __nv_bfloat16 hb = __float2bfloat16(p);
            ph[rb + j] = hb;
            pl[rb + j] = __float2bfloat16(p - __bfloat162float(hb));
        }
    }
}

// ---------------- mma.sync split-bf16 GEMM, 2-stage pipeline ----------------
// C[M,N] = (Ah+Al)[M,K] @ (Bh+Bl)[N,K]^T   (fp32 accum)
// CTA tile 128x128xBK64; 8 warps, warp tile 32x64 (grid 4m x 2n).
// EPI: 0 scores f32 batched (causal skip); 1 q/k permuted hi/lo (*alpha);
//      3 v transposed hi/lo (smem transpose, coalesced stores);
//      4 AV -> attn hi/lo (K-limited); 5 Wo+res -> f32;
//      6 bias+gelu -> hi/lo; 7 bias+res -> f32 out
template<int EPI>
__global__ __launch_bounds__(256)
void mgemm(const __nv_bfloat16* __restrict__ Ah, const __nv_bfloat16* __restrict__ Al,
           const __nv_bfloat16* __restrict__ Bh, const __nv_bfloat16* __restrict__ Bl,
           float* __restrict__ Cf, __nv_bfloat16* __restrict__ Ch, __nv_bfloat16* __restrict__ Cl,
           const float* __restrict__ bias, const float* __restrict__ res,
           int K, int lda, int ldb, float alpha, size_t sA, size_t sB)
{
    int bn = blockIdx.x, bm = blockIdx.y, z = blockIdx.z;
    if (EPI == 0 && bn > bm) return;            // causal block skip
    int Keff = K;
    if (EPI == 4) { int kl = (bm + 1) * 128; if (kl < Keff) Keff = kl; }
    const int NCH = Keff >> 6;

    extern __shared__ char smem[];
    uint32_t sb = smem_u32(smem);
    // per stage: Ah @0, Al @16K, Bh @32K, Bl @48K; stage stride 64K; 2 stages
    const uint32_t STG = 65536;

    int tid = threadIdx.x, wid = tid >> 5, lane = tid & 31;
    int wm = wid >> 1, wn = wid & 1;            // warp tile: rows wm*32, cols wn*64

    const __nv_bfloat16* Agh = Ah + (size_t)z * sA + (size_t)(bm * 128) * lda;
    const __nv_bfloat16* Agl = Al + (size_t)z * sA + (size_t)(bm * 128) * lda;
    const __nv_bfloat16* Bgh = Bh + (size_t)z * sB + (size_t)(bn * 128) * ldb;
    const __nv_bfloat16* Bgl = Bl + (size_t)z * sB + (size_t)(bn * 128) * ldb;

    auto ldst = [&](int i, int st) {
        uint32_t base = sb + st * STG;
        int k0 = i << 6;
#pragma unroll
        for (int p = tid; p < 1024; p += 256) {
            int r = p >> 3, c = p & 7;
            uint32_t so = SW128(r * 128 + c * 16);
            size_t go = (size_t)r * lda + k0 + c * 8;
            cpa16(base + so,         Agh + go);
            cpa16(base + 16384 + so, Agl + go);
        }
#pragma unroll
        for (int p = tid; p < 1024; p += 256) {
            int r = p >> 3, c = p & 7;
            uint32_t so = SW128(r * 128 + c * 16);
            size_t go = (size_t)r * ldb + k0 + c * 8;
            cpa16(base + 32768 + so, Bgh + go);
            cpa16(base + 49152 + so, Bgl + go);
        }
        cpa_commit();
    };

    float acc[2][8][4];
#pragma unroll
    for (int mi = 0; mi < 2; mi++)
#pragma unroll
        for (int ni = 0; ni < 8; ni++)
#pragma unroll
            for (int r = 0; r < 4; r++) acc[mi][ni][r] = 0.f;

    ldst(0, 0);

    for (int i = 0; i < NCH; i++) {
        int st = i & 1;
        if (i + 1 < NCH) { ldst(i + 1, (i + 1) & 1); cpa_wait<1>(); }
        else             { cpa_wait<0>(); }
        __syncthreads();

        uint32_t base = sb + st * STG;
#pragma unroll
        for (int ks = 0; ks < 4; ks++) {
            uint32_t ah[2][4], al[2][4];
#pragma unroll
            for (int mi = 0; mi < 2; mi++) {
                int row = wm * 32 + mi * 16 + (lane & 15);
                uint32_t kb = ks * 32 + ((lane >> 4) << 4);
                uint32_t ad = base + SW128((uint32_t)(row * 128) + kb);
                LDSM4(ah[mi], ad);
                LDSM4(al[mi], ad + 16384);
            }
            uint32_t bh[4][4], bl[4][4];
#pragma unroll
            for (int g = 0; g < 4; g++) {
                int nrow = wn * 64 + g * 16 + (lane & 7) + ((lane >> 4) << 3);
                uint32_t kb = ks * 32 + (((lane >> 3) & 1) << 4);
                uint32_t ad = base + 32768 + SW128((uint32_t)(nrow * 128) + kb);
                LDSM4(bh[g], ad);
                LDSM4(bl[g], ad + 16384);
            }
#pragma unroll
            for (int mi = 0; mi < 2; mi++)
#pragma unroll
                for (int ni = 0; ni < 8; ni++) {
                    uint32_t* pbh = &bh[ni >> 1][(ni & 1) * 2];
                    uint32_t* pbl = &bl[ni >> 1][(ni & 1) * 2];
                    MMA_BF16(acc[mi][ni], ah[mi], pbh);
                    MMA_BF16(acc[mi][ni], ah[mi], pbl);
                    MMA_BF16(acc[mi][ni], al[mi], pbh);
                }
        }
        __syncthreads();
    }

    // ---------------- epilogue ----------------
    if (EPI == 3) {
        // Transpose 128x128 tile via smem (stage buffers dead), then store
        // coalesced along T: out[(b*NH+hh)*128 + d][t] hi/lo.
        float* sf = (float*)smem;                       // [128][132]
#pragma unroll
        for (int mi = 0; mi < 2; mi++)
#pragma unroll
            for (int ni = 0; ni < 8; ni++)
#pragma unroll
                for (int half = 0; half < 2; half++) {
                    int r = wm * 32 + mi * 16 + (lane >> 2) + half * 8;
                    int c = wn * 64 + ni * 8 + (lane & 3) * 2;
                    sf[r * 132 + c]     = acc[mi][ni][half * 2 + 0];
                    sf[r * 132 + c + 1] = acc[mi][ni][half * 2 + 1];
                }
        __syncthreads();

        int d  = tid >> 1;                // 0..127  (output row within head)
        int t0 = (tid & 1) * 64;          // half of the 128 t values
        int b  = (bm * 128) >> 11;
        int hh = bn;                      // H_/128 == NH_
        int tloc = (bm & (T_ / 128 - 1)) * 128;   // token offset WITHIN batch
        size_t obase = ((size_t)(b * NH_ + hh) * HD_ + d) * T_ + (size_t)tloc + t0;

        uint32_t hbuf[32], lbuf[32];
#pragma unroll
        for (int q = 0; q < 32; q++) {
            float a  = sf[(t0 + 2 * q)     * 132 + d];
            float c2 = sf[(t0 + 2 * q + 1) * 132 + d];
            hbuf[q] = pack_split_hi(a, c2, &lbuf[q]);
        }
        uint4* ph4 = (uint4*)(Ch + obase);
        uint4* pl4 = (uint4*)(Cl + obase);
#pragma unroll
        for (int g = 0; g < 8; g++) {
            ph4[g] = make_uint4(hbuf[4*g], hbuf[4*g+1], hbuf[4*g+2], hbuf[4*g+3]);
            pl4[g] = make_uint4(lbuf[4*g], lbuf[4*g+1], lbuf[4*g+2], lbuf[4*g+3]);
        }
        return;
    }

#pragma unroll
    for (int mi = 0; mi < 2; mi++) {
#pragma unroll
        for (int ni = 0; ni < 8; ni++) {
            int row0 = bm * 128 + wm * 32 + mi * 16 + (lane >> 2);
            int col  = bn * 128 + wn * 64 + ni * 8 + (lane & 3) * 2;
#pragma unroll
            for (int half = 0; half < 2; half++) {
                int gm = row0 + half * 8;
                float v0 = acc[mi][ni][half * 2 + 0];
                float v1 = acc[mi][ni][half * 2 + 1];

                if (EPI == 0) {
                    float2* p = (float2*)(Cf + (size_t)z * T_ * T_ + (size_t)gm * T_ + col);
                    *p = make_float2(v0, v1);
                } else if (EPI == 1) {
                    v0 *= alpha; v1 *= alpha;
                    int b = gm >> 11, t = gm & (T_ - 1);
                    int hh = col >> 7, d = col & 127;
                    size_t idx = (((size_t)(b * NH_ + hh) * T_ + t) << 7) + d;
                    st_split2(Ch + idx, Cl + idx, v0, v1);
                } else if (EPI == 4) {
                    int b = z >> 4, hh = z & 15;
                    size_t idx = ((size_t)(b * T_ + gm)) * H_ + hh * HD_ + col;
                    st_split2(Ch + idx, Cl + idx, v0, v1);
                } else if (EPI == 5) {
                    size_t idx = (size_t)gm * H_ + col;
                    float2 rv = *(const float2*)(res + idx);
                    *(float2*)(Cf + idx) = make_float2(v0 + rv.x, v1 + rv.y);
                } else if (EPI == 6) {
                    v0 = gelu_tanh_f(v0 + bias[col]);
                    v1 = gelu_tanh_f(v1 + bias[col + 1]);
                    size_t idx = (size_t)gm * FF_ + col;
                    st_split2(Ch + idx, Cl + idx, v0, v1);
                } else if (EPI == 7) {
                    size_t idx = (size_t)gm * H_ + col;
                    float2 rv = *(const float2*)(res + idx);
                    *(float2*)(Cf + idx) =
                        make_float2(v0 + rv.x + bias[col], v1 + rv.y + bias[col + 1]);
                }
            }
        }
    }
}

// ---------------- launch ----------------
extern "C" void kernel_launch(void* const* d_in, const int* in_sizes, int n_in,
                              void* d_out, int out_size)
{
    (void)in_sizes; (void)n_in; (void)out_size;
    const float* x    = (const float*)d_in[0];
    const float* wq   = (const float*)d_in[1];
    const float* wk   = (const float*)d_in[2];
    const float* wv   = (const float*)d_in[3];
    const float* wo   = (const float*)d_in[4];
    const float* ln1s = (const float*)d_in[5];
    const float* ln1b = (const float*)d_in[6];
    const float* ln2s = (const float*)d_in[7];
    const float* ln2b = (const float*)d_in[8];
    const float* w1   = (const float*)d_in[9];
    const float* b1   = (const float*)d_in[10];
    const float* w2   = (const float*)d_in[11];
    const float* b2   = (const float*)d_in[12];
    float* out = (float*)d_out;

    __nv_bfloat16 *h_h,*h_l,*q_h,*q_l,*k_h,*k_l,*vt_h,*vt_l,*at_h,*at_l,*f_h,*f_l,*p_h,*p_l;
    __nv_bfloat16 *wqt_h,*wqt_l,*wkt_h,*wkt_l,*wvt_h,*wvt_l,*wot_h,*wot_l,*w1t_h,*w1t_l,*w2t_h,*w2t_l;
    float *x2, *sc;
    cudaGetSymbolAddress((void**)&h_h, g_h_h);   cudaGetSymbolAddress((void**)&h_l, g_h_l);
    cudaGetSymbolAddress((void**)&q_h, g_q_h);   cudaGetSymbolAddress((void**)&q_l, g_q_l);
    cudaGetSymbolAddress((void**)&k_h, g_k_h);   cudaGetSymbolAddress((void**)&k_l, g_k_l);
    cudaGetSymbolAddress((void**)&vt_h, g_vt_h); cudaGetSymbolAddress((void**)&vt_l, g_vt_l);
    cudaGetSymbolAddress((void**)&at_h, g_at_h); cudaGetSymbolAddress((void**)&at_l, g_at_l);
    cudaGetSymbolAddress((void**)&f_h, g_f_h);   cudaGetSymbolAddress((void**)&f_l, g_f_l);
    cudaGetSymbolAddress((void**)&p_h, g_p_h);   cudaGetSymbolAddress((void**)&p_l, g_p_l);
    cudaGetSymbolAddress((void**)&wqt_h, g_wq_h); cudaGetSymbolAddress((void**)&wqt_l, g_wq_l);
    cudaGetSymbolAddress((void**)&wkt_h, g_wk_h); cudaGetSymbolAddress((void**)&wkt_l, g_wk_l);
    cudaGetSymbolAddress((void**)&wvt_h, g_wv_h); cudaGetSymbolAddress((void**)&wvt_l, g_wv_l);
    cudaGetSymbolAddress((void**)&wot_h, g_wo_h); cudaGetSymbolAddress((void**)&wot_l, g_wo_l);
    cudaGetSymbolAddress((void**)&w1t_h, g_w1_h); cudaGetSymbolAddress((void**)&w1t_l, g_w1_l);
    cudaGetSymbolAddress((void**)&w2t_h, g_w2_h); cudaGetSymbolAddress((void**)&w2t_l, g_w2_l);
    cudaGetSymbolAddress((void**)&x2, g_x2);
    cudaGetSymbolAddress((void**)&sc, g_sc);

    const int SMEM = 131072;   // 2 stages x 64KB
    cudaFuncSetAttribute(mgemm<0>, cudaFuncAttributeMaxDynamicSharedMemorySize, SMEM);
    cudaFuncSetAttribute(mgemm<1>, cudaFuncAttributeMaxDynamicSharedMemorySize, SMEM);
    cudaFuncSetAttribute(mgemm<3>, cudaFuncAttributeMaxDynamicSharedMemorySize, SMEM);
    cudaFuncSetAttribute(mgemm<4>, cudaFuncAttributeMaxDynamicSharedMemorySize, SMEM);
    cudaFuncSetAttribute(mgemm<5>, cudaFuncAttributeMaxDynamicSharedMemorySize, SMEM);
    cudaFuncSetAttribute(mgemm<6>, cudaFuncAttributeMaxDynamicSharedMemorySize, SMEM);
    cudaFuncSetAttribute(mgemm<7>, cudaFuncAttributeMaxDynamicSharedMemorySize, SMEM);

    const float qscale = 0.08838834764831843f;  // 1/sqrt(128)
    dim3 tt(32, 8);

    // weight transpose+split (4 square weights batched + the two FFN weights)
    wsplitT4<<<dim3(H_/32, H_/32, 4), tt>>>(wq, wk, wv, wo,
        wqt_h, wqt_l, wkt_h, wkt_l, wvt_h, wvt_l, wot_h, wot_l);
    wsplitT<<<dim3(FF_/32, H_/32),  tt>>>(w1, w1t_h, w1t_l, H_,  FF_);
    wsplitT<<<dim3(H_/32,  FF_/32), tt>>>(w2, w2t_h, w2t_l, FF_, H_);

    // LN1
    ln_kernel<<<M_, 256>>>(x, ln1s, ln1b, h_h, h_l);

    // QKV (q,k: EPI1 permuted; v: EPI3 transposed via smem)
    dim3 gqkv(H_/128, M_/128);
    mgemm<1><<<gqkv, 256, SMEM>>>(h_h, h_l, wqt_h, wqt_l, nullptr, q_h, q_l,
                                  nullptr, nullptr, H_, H_, H_, qscale, 0, 0);
    mgemm<1><<<gqkv, 256, SMEM>>>(h_h, h_l, wkt_h, wkt_l, nullptr, k_h, k_l,
                                  nullptr, nullptr, H_, H_, H_, 1.0f, 0, 0);
    mgemm<3><<<gqkv, 256, SMEM>>>(h_h, h_l, wvt_h, wvt_l, nullptr, vt_h, vt_l,
                                  nullptr, nullptr, H_, H_, H_, 1.0f, 0, 0);

    // scores = q @ k^T (batched, causal block skip)
    dim3 gsc(T_/128, T_/128, NBATCH);
    mgemm<0><<<gsc, 256, SMEM>>>(q_h, q_l, k_h, k_l, sc, nullptr, nullptr,
                                 nullptr, nullptr, HD_, HD_, HD_, 1.0f,
                                 (size_t)T_*HD_, (size_t)T_*HD_);

    // softmax -> probs hi/lo
    softmax_kernel<<<NBATCH * T_, 256>>>(sc, p_h, p_l);

    // attn = P @ V (K-limited)
    dim3 gav(1, T_/128, NBATCH);
    mgemm<4><<<gav, 256, SMEM>>>(p_h, p_l, vt_h, vt_l, nullptr, at_h, at_l,
                                 nullptr, nullptr, T_, T_, T_, 1.0f,
                                 (size_t)T_*T_, (size_t)HD_*T_);

    // x2 = x + attn @ wo
    mgemm<5><<<gqkv, 256, SMEM>>>(at_h, at_l, wot_h, wot_l, x2, nullptr, nullptr,
                                  nullptr, x, H_, H_, H_, 1.0f, 0, 0);

    // LN2
    ln_kernel<<<M_, 256>>>(x2, ln2s, ln2b, h_h, h_l);

    // ffn = gelu(h @ w1 + b1)
    dim3 gf1(FF_/128, M_/128);
    mgemm<6><<<gf1, 256, SMEM>>>(h_h, h_l, w1t_h, w1t_l, nullptr, f_h, f_l,
                                 b1, nullptr, H_, H_, H_, 1.0f, 0, 0);

    // out = x2 + ffn @ w2 + b2
    dim3 gf2(H_/128, M_/128);
    mgemm<7><<<gf2, 256, SMEM>>>(f_h, f_l, w2t_h, w2t_l, out, nullptr, nullptr,
                                 b2, x2, FF_, FF_, FF_, 1.0f, 0, 0);
}

// round 9
// speedup vs baseline: 1.0986x; 1.0521x over previous
#include <cuda_runtime.h>
#include <cuda_bf16.h>
#include <math.h>
#include <stdint.h>

// Problem constants
#define B_   2
#define T_   2048
#define H_   2048
#define NH_  16
#define HD_  128
#define FF_  8192
#define M_   (B_*T_)       // 4096
#define NBATCH (B_*NH_)    // 32
#define EPS_ 1e-5f

// ---------------- scratch (static device globals) ----------------
__device__ __align__(128) __nv_bfloat16 g_h_h [(size_t)M_*H_];
__device__ __align__(128) __nv_bfloat16 g_h_l [(size_t)M_*H_];
__device__ __align__(128) __nv_bfloat16 g_qk_h[(size_t)2*M_*H_];  // q then k, [B,NH,T,HD]
__device__ __align__(128) __nv_bfloat16 g_qk_l[(size_t)2*M_*H_];
__device__ __align__(128) __nv_bfloat16 g_vt_h[(size_t)M_*H_];    // [B,NH,HD,T]
__device__ __align__(128) __nv_bfloat16 g_vt_l[(size_t)M_*H_];
__device__ __align__(128) __nv_bfloat16 g_at_h[(size_t)M_*H_];    // attn [B,T,H]
__device__ __align__(128) __nv_bfloat16 g_at_l[(size_t)M_*H_];
__device__ __align__(128) __nv_bfloat16 g_f_h [(size_t)M_*FF_];
__device__ __align__(128) __nv_bfloat16 g_f_l [(size_t)M_*FF_];
__device__ __align__(128) float g_x2[(size_t)M_*H_];
__device__ __align__(128) float g_sc[(size_t)NBATCH*T_*T_];       // scores; later split-K partials
__device__ __align__(128) __nv_bfloat16 g_p_h[(size_t)NBATCH*T_*T_];
__device__ __align__(128) __nv_bfloat16 g_p_l[(size_t)NBATCH*T_*T_];
// transposed split weights [N,K]
__device__ __align__(128) __nv_bfloat16 g_wqk_h[(size_t)2*H_*H_]; // wq then wk
__device__ __align__(128) __nv_bfloat16 g_wqk_l[(size_t)2*H_*H_];
__device__ __align__(128) __nv_bfloat16 g_wv_h[(size_t)H_*H_];
__device__ __align__(128) __nv_bfloat16 g_wv_l[(size_t)H_*H_];
__device__ __align__(128) __nv_bfloat16 g_wo_h[(size_t)H_*H_];
__device__ __align__(128) __nv_bfloat16 g_wo_l[(size_t)H_*H_];
__device__ __align__(128) __nv_bfloat16 g_w1_h[(size_t)FF_*H_];
__device__ __align__(128) __nv_bfloat16 g_w1_l[(size_t)FF_*H_];
__device__ __align__(128) __nv_bfloat16 g_w2_h[(size_t)H_*FF_];
__device__ __align__(128) __nv_bfloat16 g_w2_l[(size_t)H_*FF_];

// ---------------- PTX helpers (all arch-portable: sm_80+) ----------------
__device__ __forceinline__ uint32_t smem_u32(const void* p) {
    uint32_t a;
    asm("{ .reg .u64 t; cvta.to.shared.u64 t, %1; cvt.u32.u64 %0, t; }" : "=r"(a) : "l"(p));
    return a;
}
#define SW128(o) ((o) ^ (((o) >> 3) & 0x70))

__device__ __forceinline__ void cpa16(uint32_t s, const void* g) {
    asm volatile("cp.async.cg.shared.global [%0], [%1], 16;" :: "r"(s), "l"(g) : "memory");
}
__device__ __forceinline__ void cpa_commit() {
    asm volatile("cp.async.commit_group;" ::: "memory");
}
template<int N> __device__ __forceinline__ void cpa_wait() {
    asm volatile("cp.async.wait_group %0;" :: "n"(N) : "memory");
}

#define LDSM4(r, addr) \
    asm volatile("ldmatrix.sync.aligned.m8n8.x4.shared.b16 {%0,%1,%2,%3}, [%4];" \
        : "=r"((r)[0]), "=r"((r)[1]), "=r"((r)[2]), "=r"((r)[3]) : "r"(addr))

#define MMA_BF16(d, a, b) \
    asm volatile("mma.sync.aligned.m16n8k16.row.col.f32.bf16.bf16.f32 " \
        "{%0,%1,%2,%3},{%4,%5,%6,%7},{%8,%9},{%0,%1,%2,%3};" \
        : "+f"((d)[0]), "+f"((d)[1]), "+f"((d)[2]), "+f"((d)[3]) \
        : "r"((a)[0]), "r"((a)[1]), "r"((a)[2]), "r"((a)[3]), "r"((b)[0]), "r"((b)[1]))

// ---------------- misc helpers ----------------
__device__ __forceinline__ float gelu_tanh_f(float x) {
    float x3 = x * x * x;
    float t  = tanhf(0.7978845608028654f * (x + 0.044715f * x3));
    return 0.5f * x * (1.0f + t);
}
__device__ __forceinline__ void st_split2(__nv_bfloat16* ph, __nv_bfloat16* pl, float a, float b) {
    __nv_bfloat16 ha = __float2bfloat16(a), hb = __float2bfloat16(b);
    __nv_bfloat162 hp = __halves2bfloat162(ha, hb);
    __nv_bfloat162 lp = __halves2bfloat162(__float2bfloat16(a - __bfloat162float(ha)),
                                           __float2bfloat16(b - __bfloat162float(hb)));
    *(uint32_t*)ph = *(uint32_t*)&hp;
    *(uint32_t*)pl = *(uint32_t*)&lp;
}
__device__ __forceinline__ uint32_t pack_split_hi(float a, float b, uint32_t* lo) {
    __nv_bfloat16 ha = __float2bfloat16(a), hb = __float2bfloat16(b);
    __nv_bfloat162 hp = __halves2bfloat162(ha, hb);
    __nv_bfloat162 lp = __halves2bfloat162(__float2bfloat16(a - __bfloat162float(ha)),
                                           __float2bfloat16(b - __bfloat162float(hb)));
    *lo = *(uint32_t*)&lp;
    return *(uint32_t*)&hp;
}

// ---------------- weight transpose + split: W[K,N] f32 -> T[N,K] bf16 hi/lo ----------------
__global__ __launch_bounds__(256)
void wsplitT(const float* __restrict__ W, __nv_bfloat16* __restrict__ Th,
             __nv_bfloat16* __restrict__ Tl, int K, int N)
{
    __shared__ float t[32][33];
    int n0 = blockIdx.x * 32, k0 = blockIdx.y * 32;
    int tx = threadIdx.x, ty = threadIdx.y;   // (32,8)
#pragma unroll
    for (int r = ty; r < 32; r += 8)
        t[r][tx] = W[(size_t)(k0 + r) * N + n0 + tx];
    __syncthreads();
#pragma unroll
    for (int r = ty; r < 32; r += 8) {
        float v = t[tx][r];
        __nv_bfloat16 h = __float2bfloat16(v);
        size_t idx = (size_t)(n0 + r) * K + k0 + tx;
        Th[idx] = h;
        Tl[idx] = __float2bfloat16(v - __bfloat162float(h));
    }
}

// batched version for the four HxH weights (z = which weight)
__global__ __launch_bounds__(256)
void wsplitT4(const float* __restrict__ w0, const float* __restrict__ w1,
              const float* __restrict__ w2, const float* __restrict__ w3,
              __nv_bfloat16* __restrict__ t0h, __nv_bfloat16* __restrict__ t0l,
              __nv_bfloat16* __restrict__ t1h, __nv_bfloat16* __restrict__ t1l,
              __nv_bfloat16* __restrict__ t2h, __nv_bfloat16* __restrict__ t2l,
              __nv_bfloat16* __restrict__ t3h, __nv_bfloat16* __restrict__ t3l)
{
    __shared__ float t[32][33];
    int z = blockIdx.z;
    const float* W = (z == 0) ? w0 : (z == 1) ? w1 : (z == 2) ? w2 : w3;
    __nv_bfloat16* Th = (z == 0) ? t0h : (z == 1) ? t1h : (z == 2) ? t2h : t3h;
    __nv_bfloat16* Tl = (z == 0) ? t0l : (z == 1) ? t1l : (z == 2) ? t2l : t3l;
    int n0 = blockIdx.x * 32, k0 = blockIdx.y * 32;
    int tx = threadIdx.x, ty = threadIdx.y;
#pragma unroll
    for (int r = ty; r < 32; r += 8)
        t[r][tx] = W[(size_t)(k0 + r) * H_ + n0 + tx];
    __syncthreads();
#pragma unroll
    for (int r = ty; r < 32; r += 8) {
        float v = t[tx][r];
        __nv_bfloat16 h = __float2bfloat16(v);
        size_t idx = (size_t)(n0 + r) * H_ + k0 + tx;
        Th[idx] = h;
        Tl[idx] = __float2bfloat16(v - __bfloat162float(h));
    }
}

// ---------------- LayerNorm -> bf16 hi/lo ----------------
__global__ __launch_bounds__(256)
void ln_kernel(const float* __restrict__ x, const float* __restrict__ sc,
               const float* __restrict__ sh,
               __nv_bfloat16* __restrict__ oh, __nv_bfloat16* __restrict__ ol)
{
    __shared__ float red[8];
    int row = blockIdx.x;
    int tid = threadIdx.x;
    const float* xr = x + (size_t)row * H_;

    float v[8];
    float s = 0.f;
#pragma unroll
    for (int i = 0; i < 8; i++) { v[i] = xr[i * 256 + tid]; s += v[i]; }
#pragma unroll
    for (int o = 16; o > 0; o >>= 1) s += __shfl_xor_sync(0xffffffffu, s, o);
    if ((tid & 31) == 0) red[tid >> 5] = s;
    __syncthreads();
    float tot = 0.f;
#pragma unroll
    for (int i = 0; i < 8; i++) tot += red[i];
    __syncthreads();
    float mean = tot * (1.0f / H_);

    float s2 = 0.f;
#pragma unroll
    for (int i = 0; i < 8; i++) { float d = v[i] - mean; s2 += d * d; }
#pragma unroll
    for (int o = 16; o > 0; o >>= 1) s2 += __shfl_xor_sync(0xffffffffu, s2, o);
    if ((tid & 31) == 0) red[tid >> 5] = s2;
    __syncthreads();
    float tot2 = 0.f;
#pragma unroll
    for (int i = 0; i < 8; i++) tot2 += red[i];

    float inv = rsqrtf(tot2 * (1.0f / H_) + EPS_);
    size_t rb = (size_t)row * H_;
#pragma unroll
    for (int i = 0; i < 8; i++) {
        int col = i * 256 + tid;
        float val = sc[col] * ((v[i] - mean) * inv) + sh[col];
        __nv_bfloat16 h = __float2bfloat16(val);
        oh[rb + col] = h;
        ol[rb + col] = __float2bfloat16(val - __bfloat162float(h));
    }
}

// ---------------- causal softmax: f32 scores -> bf16 hi/lo probs ----------------
__global__ __launch_bounds__(256)
void softmax_kernel(const float* __restrict__ sc,
                    __nv_bfloat16* __restrict__ ph, __nv_bfloat16* __restrict__ pl)
{
    __shared__ float red[8];
    int gid = blockIdx.x;
    int i   = gid & (T_ - 1);
    int tid = threadIdx.x;
    const float* row = sc + (size_t)gid * T_;

    int n = i + 1;
    int kround = ((i >> 7) + 1) << 7;

    float v[8];
    float mx = -1e30f;
#pragma unroll
    for (int s = 0; s < 8; s++) {
        int j = s * 256 + tid;
        v[s] = (j < n) ? row[j] : -1e30f;
        mx = fmaxf(mx, v[s]);
    }
#pragma unroll
    for (int o = 16; o > 0; o >>= 1) mx = fmaxf(mx, __shfl_xor_sync(0xffffffffu, mx, o));
    if ((tid & 31) == 0) red[tid >> 5] = mx;
    __syncthreads();
    float m2 = -1e30f;
#pragma unroll
    for (int w = 0; w < 8; w++) m2 = fmaxf(m2, red[w]);
    __syncthreads();

    float sum = 0.f;
#pragma unroll
    for (int s = 0; s < 8; s++) {
        int j = s * 256 + tid;
        if (j < n) { v[s] = __expf(v[s] - m2); sum += v[s]; }
        else       { v[s] = 0.f; }
    }
#pragma unroll
    for (int o = 16; o > 0; o >>= 1) sum += __shfl_xor_sync(0xffffffffu, sum, o);
    if ((tid & 31) == 0) red[tid >> 5] = sum;
    __syncthreads();
    float tot = 0.f;
#pragma unroll
    for (int w = 0; w < 8; w++) tot += red[w];

    float inv = 1.0f / tot;
    size_t rb = (size_t)gid * T_;
#pragma unroll
    for (int s = 0; s < 8; s++) {
        int j = s * 256 + tid;
        if (j < kround) {
            float p = v[s] * inv;
            __nv_bfloat16 hb = __float2bfloat16(p);
            ph[rb + j] = hb;
            pl[rb + j] = __float2bfloat16(p - __bfloat162float(hb));
        }
    }
}

// ---------------- split-K combine: out = p0 + p1 + res (+ bias) ----------------
__global__ __launch_bounds__(256)
void combine2(const float* __restrict__ p0, const float* __restrict__ p1,
              const float* __restrict__ res, const float* __restrict__ bias,
              float* __restrict__ out)
{
    size_t i4 = (size_t)blockIdx.x * 256 + threadIdx.x;
    size_t base = i4 * 4;
    float4 a = *(const float4*)(p0 + base);
    float4 b = *(const float4*)(p1 + base);
    float4 r = *(const float4*)(res + base);
    float4 o;
    o.x = a.x + b.x + r.x;
    o.y = a.y + b.y + r.y;
    o.z = a.z + b.z + r.z;
    o.w = a.w + b.w + r.w;
    if (bias) {
        int col = (int)(base & (H_ - 1));
        o.x += bias[col]; o.y += bias[col + 1]; o.z += bias[col + 2]; o.w += bias[col + 3];
    }
    *(float4*)(out + base) = o;
}

// ---------------- mma.sync split-bf16 GEMM, 2-stage pipeline ----------------
// C[M,N] = (Ah+Al)[M,K] @ (Bh+Bl)[N,K]^T   (fp32 accum)
// CTA tile 128x128xBK64; 8 warps, warp tile 32x64 (grid 4m x 2n).
// EPI: 0 scores f32 batched (causal skip); 1 q/k permuted hi/lo (z: q *alpha, k *1);
//      3 v transposed hi/lo (smem transpose, coalesced stores);
//      4 AV -> attn hi/lo (K-limited, bm reversed for balance);
//      6 bias+gelu -> hi/lo; 8 split-K f32 partial (z = k-half)
template<int EPI>
__global__ __launch_bounds__(256)
void mgemm(const __nv_bfloat16* __restrict__ Ah, const __nv_bfloat16* __restrict__ Al,
           const __nv_bfloat16* __restrict__ Bh, const __nv_bfloat16* __restrict__ Bl,
           float* __restrict__ Cf, __nv_bfloat16* __restrict__ Ch, __nv_bfloat16* __restrict__ Cl,
           const float* __restrict__ bias, const float* __restrict__ res,
           int K, int lda, int ldb, float alpha, size_t sA, size_t sB)
{
    int bn = blockIdx.x, bm = blockIdx.y, z = blockIdx.z;
    if (EPI == 4) bm = gridDim.y - 1 - bm;      // longest-K tiles first
    if (EPI == 0 && bn > bm) return;            // causal block skip
    int Keff = K;
    if (EPI == 4) { int kl = (bm + 1) * 128; if (kl < Keff) Keff = kl; }
    const int NCH = Keff >> 6;

    extern __shared__ char smem[];
    uint32_t sb = smem_u32(smem);
    // per stage: Ah @0, Al @16K, Bh @32K, Bl @48K; stage stride 64K; 2 stages
    const uint32_t STG = 65536;

    int tid = threadIdx.x, wid = tid >> 5, lane = tid & 31;
    int wm = wid >> 1, wn = wid & 1;            // warp tile: rows wm*32, cols wn*64

    const __nv_bfloat16* Agh = Ah + (size_t)z * sA + (size_t)(bm * 128) * lda;
    const __nv_bfloat16* Agl = Al + (size_t)z * sA + (size_t)(bm * 128) * lda;
    const __nv_bfloat16* Bgh = Bh + (size_t)z * sB + (size_t)(bn * 128) * ldb;
    const __nv_bfloat16* Bgl = Bl + (size_t)z * sB + (size_t)(bn * 128) * ldb;

    auto ldst = [&](int i, int st) {
        uint32_t base = sb + st * STG;
        int k0 = i << 6;
#pragma unroll
        for (int p = tid; p < 1024; p += 256) {
            int r = p >> 3, c = p & 7;
            uint32_t so = SW128(r * 128 + c * 16);
            size_t go = (size_t)r * lda + k0 + c * 8;
            cpa16(base + so,         Agh + go);
            cpa16(base + 16384 + so, Agl + go);
        }
#pragma unroll
        for (int p = tid; p < 1024; p += 256) {
            int r = p >> 3, c = p & 7;
            uint32_t so = SW128(r * 128 + c * 16);
            size_t go = (size_t)r * ldb + k0 + c * 8;
            cpa16(base + 32768 + so, Bgh + go);
            cpa16(base + 49152 + so, Bgl + go);
        }
        cpa_commit();
    };

    float acc[2][8][4];
#pragma unroll
    for (int mi = 0; mi < 2; mi++)
#pragma unroll
        for (int ni = 0; ni < 8; ni++)
#pragma unroll
            for (int r = 0; r < 4; r++) acc[mi][ni][r] = 0.f;

    ldst(0, 0);

    for (int i = 0; i < NCH; i++) {
        int st = i & 1;
        if (i + 1 < NCH) { ldst(i + 1, (i + 1) & 1); cpa_wait<1>(); }
        else             { cpa_wait<0>(); }
        __syncthreads();

        uint32_t base = sb + st * STG;
#pragma unroll
        for (int ks = 0; ks < 4; ks++) {
            uint32_t ah[2][4], al[2][4];
#pragma unroll
            for (int mi = 0; mi < 2; mi++) {
                int row = wm * 32 + mi * 16 + (lane & 15);
                uint32_t kb = ks * 32 + ((lane >> 4) << 4);
                uint32_t ad = base + SW128((uint32_t)(row * 128) + kb);
                LDSM4(ah[mi], ad);
                LDSM4(al[mi], ad + 16384);
            }
            uint32_t bh[4][4], bl[4][4];
#pragma unroll
            for (int g = 0; g < 4; g++) {
                int nrow = wn * 64 + g * 16 + (lane & 7) + ((lane >> 4) << 3);
                uint32_t kb = ks * 32 + (((lane >> 3) & 1) << 4);
                uint32_t ad = base + 32768 + SW128((uint32_t)(nrow * 128) + kb);
                LDSM4(bh[g], ad);
                LDSM4(bl[g], ad + 16384);
            }
#pragma unroll
            for (int mi = 0; mi < 2; mi++)
#pragma unroll
                for (int ni = 0; ni < 8; ni++) {
                    uint32_t* pbh = &bh[ni >> 1][(ni & 1) * 2];
                    uint32_t* pbl = &bl[ni >> 1][(ni & 1) * 2];
                    MMA_BF16(acc[mi][ni], ah[mi], pbh);
                    MMA_BF16(acc[mi][ni], ah[mi], pbl);
                    MMA_BF16(acc[mi][ni], al[mi], pbh);
                }
        }
        __syncthreads();
    }

    // ---------------- epilogue ----------------
    if (EPI == 3) {
        // Transpose 128x128 tile via smem (stage buffers dead), coalesced stores along T.
        float* sf = (float*)smem;                       // [128][132]
#pragma unroll
        for (int mi = 0; mi < 2; mi++)
#pragma unroll
            for (int ni = 0; ni < 8; ni++)
#pragma unroll
                for (int half = 0; half < 2; half++) {
                    int r = wm * 32 + mi * 16 + (lane >> 2) + half * 8;
                    int c = wn * 64 + ni * 8 + (lane & 3) * 2;
                    sf[r * 132 + c]     = acc[mi][ni][half * 2 + 0];
                    sf[r * 132 + c + 1] = acc[mi][ni][half * 2 + 1];
                }
        __syncthreads();

        int d  = tid >> 1;
        int t0 = (tid & 1) * 64;
        int b  = (bm * 128) >> 11;
        int hh = bn;                              // H_/128 == NH_
        int tloc = (bm & (T_ / 128 - 1)) * 128;   // token offset WITHIN batch
        size_t obase = ((size_t)(b * NH_ + hh) * HD_ + d) * T_ + (size_t)tloc + t0;

        uint32_t hbuf[32], lbuf[32];
#pragma unroll
        for (int q = 0; q < 32; q++) {
            float a  = sf[(t0 + 2 * q)     * 132 + d];
            float c2 = sf[(t0 + 2 * q + 1) * 132 + d];
            hbuf[q] = pack_split_hi(a, c2, &lbuf[q]);
        }
        uint4* ph4 = (uint4*)(Ch + obase);
        uint4* pl4 = (uint4*)(Cl + obase);
#pragma unroll
        for (int g = 0; g < 8; g++) {
            ph4[g] = make_uint4(hbuf[4*g], hbuf[4*g+1], hbuf[4*g+2], hbuf[4*g+3]);
            pl4[g] = make_uint4(lbuf[4*g], lbuf[4*g+1], lbuf[4*g+2], lbuf[4*g+3]);
        }
        return;
    }

#pragma unroll
    for (int mi = 0; mi < 2; mi++) {
#pragma unroll
        for (int ni = 0; ni < 8; ni++) {
            int row0 = bm * 128 + wm * 32 + mi * 16 + (lane >> 2);
            int col  = bn * 128 + wn * 64 + ni * 8 + (lane & 3) * 2;
#pragma unroll
            for (int half = 0; half < 2; half++) {
                int gm = row0 + half * 8;
                float v0 = acc[mi][ni][half * 2 + 0];
                float v1 = acc[mi][ni][half * 2 + 1];

                if (EPI == 0) {
                    float2* p = (float2*)(Cf + (size_t)z * T_ * T_ + (size_t)gm * T_ + col);
                    *p = make_float2(v0, v1);
                } else if (EPI == 1) {
                    float a = (z == 0) ? alpha : 1.0f;
                    v0 *= a; v1 *= a;
                    int b = gm >> 11, t = gm & (T_ - 1);
                    int hh = col >> 7, d = col & 127;
                    size_t idx = (size_t)z * M_ * H_ +
                                 (((size_t)(b * NH_ + hh) * T_ + t) << 7) + d;
                    st_split2(Ch + idx, Cl + idx, v0, v1);
                } else if (EPI == 4) {
                    int b = z >> 4, hh = z & 15;
                    size_t idx = ((size_t)(b * T_ + gm)) * H_ + hh * HD_ + col;
                    st_split2(Ch + idx, Cl + idx, v0, v1);
                } else if (EPI == 6) {
                    v0 = gelu_tanh_f(v0 + bias[col]);
                    v1 = gelu_tanh_f(v1 + bias[col + 1]);
                    size_t idx = (size_t)gm * FF_ + col;
                    st_split2(Ch + idx, Cl + idx, v0, v1);
                } else if (EPI == 8) {
                    // split-K f32 partial: z selects the partial buffer
                    float2* p = (float2*)(Cf + (size_t)z * M_ * H_ + (size_t)gm * H_ + col);
                    *p = make_float2(v0, v1);
                }
            }
        }
    }
}

// ---------------- launch ----------------
extern "C" void kernel_launch(void* const* d_in, const int* in_sizes, int n_in,
                              void* d_out, int out_size)
{
    (void)in_sizes; (void)n_in; (void)out_size;
    const float* x    = (const float*)d_in[0];
    const float* wq   = (const float*)d_in[1];
    const float* wk   = (const float*)d_in[2];
    const float* wv   = (const float*)d_in[3];
    const float* wo   = (const float*)d_in[4];
    const float* ln1s = (const float*)d_in[5];
    const float* ln1b = (const float*)d_in[6];
    const float* ln2s = (const float*)d_in[7];
    const float* ln2b = (const float*)d_in[8];
    const float* w1   = (const float*)d_in[9];
    const float* b1   = (const float*)d_in[10];
    const float* w2   = (const float*)d_in[11];
    const float* b2   = (const float*)d_in[12];
    float* out = (float*)d_out;

    __nv_bfloat16 *h_h,*h_l,*qk_h,*qk_l,*vt_h,*vt_l,*at_h,*at_l,*f_h,*f_l,*p_h,*p_l;
    __nv_bfloat16 *wqk_h,*wqk_l,*wvt_h,*wvt_l,*wot_h,*wot_l,*w1t_h,*w1t_l,*w2t_h,*w2t_l;
    float *x2, *sc;
    cudaGetSymbolAddress((void**)&h_h, g_h_h);   cudaGetSymbolAddress((void**)&h_l, g_h_l);
    cudaGetSymbolAddress((void**)&qk_h, g_qk_h); cudaGetSymbolAddress((void**)&qk_l, g_qk_l);
    cudaGetSymbolAddress((void**)&vt_h, g_vt_h); cudaGetSymbolAddress((void**)&vt_l, g_vt_l);
    cudaGetSymbolAddress((void**)&at_h, g_at_h); cudaGetSymbolAddress((void**)&at_l, g_at_l);
    cudaGetSymbolAddress((void**)&f_h, g_f_h);   cudaGetSymbolAddress((void**)&f_l, g_f_l);
    cudaGetSymbolAddress((void**)&p_h, g_p_h);   cudaGetSymbolAddress((void**)&p_l, g_p_l);
    cudaGetSymbolAddress((void**)&wqk_h, g_wqk_h); cudaGetSymbolAddress((void**)&wqk_l, g_wqk_l);
    cudaGetSymbolAddress((void**)&wvt_h, g_wv_h); cudaGetSymbolAddress((void**)&wvt_l, g_wv_l);
    cudaGetSymbolAddress((void**)&wot_h, g_wo_h); cudaGetSymbolAddress((void**)&wot_l, g_wo_l);
    cudaGetSymbolAddress((void**)&w1t_h, g_w1_h); cudaGetSymbolAddress((void**)&w1t_l, g_w1_l);
    cudaGetSymbolAddress((void**)&w2t_h, g_w2_h); cudaGetSymbolAddress((void**)&w2t_l, g_w2_l);
    cudaGetSymbolAddress((void**)&x2, g_x2);
    cudaGetSymbolAddress((void**)&sc, g_sc);

    const int SMEM = 131072;   // 2 stages x 64KB
    cudaFuncSetAttribute(mgemm<0>, cudaFuncAttributeMaxDynamicSharedMemorySize, SMEM);
    cudaFuncSetAttribute(mgemm<1>, cudaFuncAttributeMaxDynamicSharedMemorySize, SMEM);
    cudaFuncSetAttribute(mgemm<3>, cudaFuncAttributeMaxDynamicSharedMemorySize, SMEM);
    cudaFuncSetAttribute(mgemm<4>, cudaFuncAttributeMaxDynamicSharedMemorySize, SMEM);
    cudaFuncSetAttribute(mgemm<6>, cudaFuncAttributeMaxDynamicSharedMemorySize, SMEM);
    cudaFuncSetAttribute(mgemm<8>, cudaFuncAttributeMaxDynamicSharedMemorySize, SMEM);

    const float qscale = 0.08838834764831843f;  // 1/sqrt(128)
    dim3 tt(32, 8);

    // weight transpose+split (wq,wk into contiguous wqk; wv, wo; then FFN weights)
    wsplitT4<<<dim3(H_/32, H_/32, 4), tt>>>(wq, wk, wv, wo,
        wqk_h, wqk_l, wqk_h + (size_t)H_*H_, wqk_l + (size_t)H_*H_,
        wvt_h, wvt_l, wot_h, wot_l);
    wsplitT<<<dim3(FF_/32, H_/32),  tt>>>(w1, w1t_h, w1t_l, H_,  FF_);
    wsplitT<<<dim3(H_/32,  FF_/32), tt>>>(w2, w2t_h, w2t_l, FF_, H_);

    // LN1
    ln_kernel<<<M_, 256>>>(x, ln1s, ln1b, h_h, h_l);

    // Q+K merged (z = 0:q scaled, 1:k); V separate (EPI3 transposed)
    dim3 gqk(H_/128, M_/128, 2);
    mgemm<1><<<gqk, 256, SMEM>>>(h_h, h_l, wqk_h, wqk_l, nullptr, qk_h, qk_l,
                                 nullptr, nullptr, H_, H_, H_, qscale,
                                 0, (size_t)H_*H_);
    dim3 gv(H_/128, M_/128);
    mgemm<3><<<gv, 256, SMEM>>>(h_h, h_l, wvt_h, wvt_l, nullptr, vt_h, vt_l,
                                nullptr, nullptr, H_, H_, H_, 1.0f, 0, 0);

    // scores = q @ k^T (batched, causal block skip); k lives at qk + M*H
    dim3 gsc(T_/128, T_/128, NBATCH);
    mgemm<0><<<gsc, 256, SMEM>>>(qk_h, qk_l, qk_h + (size_t)M_*H_, qk_l + (size_t)M_*H_,
                                 sc, nullptr, nullptr, nullptr, nullptr,
                                 HD_, HD_, HD_, 1.0f,
                                 (size_t)T_*HD_, (size_t)T_*HD_);

    // softmax -> probs hi/lo
    softmax_kernel<<<NBATCH * T_, 256>>>(sc, p_h, p_l);

    // attn = P @ V (K-limited, longest-first)
    dim3 gav(1, T_/128, NBATCH);
    mgemm<4><<<gav, 256, SMEM>>>(p_h, p_l, vt_h, vt_l, nullptr, at_h, at_l,
                                 nullptr, nullptr, T_, T_, T_, 1.0f,
                                 (size_t)T_*T_, (size_t)HD_*T_);

    // Wo split-K=2: partials into sc, combine adds residual x -> x2
    dim3 gwo(H_/128, M_/128, 2);
    mgemm<8><<<gwo, 256, SMEM>>>(at_h, at_l, wot_h, wot_l, sc, nullptr, nullptr,
                                 nullptr, nullptr, H_/2, H_, H_, 1.0f,
                                 (size_t)(H_/2), (size_t)(H_/2));
    combine2<<<(M_*H_)/1024, 256>>>(sc, sc + (size_t)M_*H_, x, nullptr, x2);

    // LN2
    ln_kernel<<<M_, 256>>>(x2, ln2s, ln2b, h_h, h_l);

    // ffn = gelu(h @ w1 + b1)
    dim3 gf1(FF_/128, M_/128);
    mgemm<6><<<gf1, 256, SMEM>>>(h_h, h_l, w1t_h, w1t_l, nullptr, f_h, f_l,
                                 b1, nullptr, H_, H_, H_, 1.0f, 0, 0);

    // FFN2 split-K=2: partials into sc, combine adds x2 + b2 -> out
    dim3 gf2(H_/128, M_/128, 2);
    mgemm<8><<<gf2, 256, SMEM>>>(f_h, f_l, w2t_h, w2t_l, sc, nullptr, nullptr,
                                 nullptr, nullptr, FF_/2, FF_, FF_, 1.0f,
                                 (size_t)(FF_/2), (size_t)(FF_/2));
    combine2<<<(M_*H_)/1024, 256>>>(sc, sc + (size_t)M_*H_, x2, b2, out);
}